// round 8
// baseline (speedup 1.0000x reference)
#include <cuda_runtime.h>
#include <cuda_bf16.h>
#include <cstdint>

#define N_NODES 50000
#define N_EDGES 800000
#define DIN     369
#define D       128
#define D3      384
#define TT      13
#define STEPS   8
#define NG      256
#define NTILE64 782              // ceil(50000/64)
#define NROWS   (TT * N_NODES)   // 650000
#define NBLK    635              // ceil(NROWS/1024)

// ================= static scratch =================
__device__ float d_H[TT * N_NODES * D];
__device__ float d_S[TT * N_NODES * D];
__device__ float d_Q[TT * STEPS * D * D3];              // [ts][k=128][n=384]
__device__ float d_R[TT * D * D3];                      // [t][k=128][j=384]
__device__ __align__(16) __nv_bfloat16 d_Bs[(size_t)TT * STEPS * 512 * 256]; // [ts][n][k]
__device__ int   d_rowptr[NROWS + 1];
__device__ int   d_rcnt[NROWS];
__device__ int   d_rcur[NROWS];
__device__ int   d_col[N_EDGES];
__device__ int   d_bsum[NBLK + 1];
__device__ float d_pool[NG * D];
__device__ float d_cnt[NG];

// ================= helpers =================
__device__ __forceinline__ uint32_t smem_u32(const void* p) {
    uint32_t a;
    asm("{ .reg .u64 t; cvta.to.shared.u64 t, %1; cvt.u32.u64 %0, t; }" : "=r"(a) : "l"(p));
    return a;
}
__device__ __forceinline__ void ldsm4(uint32_t a[4], uint32_t addr) {
    asm volatile("ldmatrix.sync.aligned.m8n8.x4.shared.b16 {%0,%1,%2,%3}, [%4];"
                 : "=r"(a[0]), "=r"(a[1]), "=r"(a[2]), "=r"(a[3]) : "r"(addr));
}
__device__ __forceinline__ void mma16816(float c[4], const uint32_t a[4],
                                         uint32_t b0, uint32_t b1) {
    asm volatile("mma.sync.aligned.m16n8k16.row.col.f32.bf16.bf16.f32 "
                 "{%0,%1,%2,%3}, {%4,%5,%6,%7}, {%8,%9}, {%0,%1,%2,%3};"
                 : "+f"(c[0]), "+f"(c[1]), "+f"(c[2]), "+f"(c[3])
                 : "r"(a[0]), "r"(a[1]), "r"(a[2]), "r"(a[3]), "r"(b0), "r"(b1));
}
__device__ __forceinline__ unsigned bf2pack(float a, float b) {
    __nv_bfloat16 x = __float2bfloat16(a), y = __float2bfloat16(b);
    return (unsigned)__bfloat16_as_ushort(x) | ((unsigned)__bfloat16_as_ushort(y) << 16);
}
__device__ __forceinline__ void fma2(unsigned long long& d,
                                     unsigned long long a, unsigned long long b) {
    asm("fma.rn.f32x2 %0, %1, %2, %0;" : "+l"(d) : "l"(a), "l"(b));
}
__device__ __forceinline__ unsigned long long dup2(float v) {
    unsigned int u = __float_as_uint(v);
    return ((unsigned long long)u << 32) | u;
}
__device__ __forceinline__ unsigned long long pack2(float lo, float hi) {
    return ((unsigned long long)__float_as_uint(hi) << 32) | __float_as_uint(lo);
}
__device__ __forceinline__ float2 u2f2(unsigned long long u) {
    float2 f;
    f.x = __uint_as_float((unsigned int)u);
    f.y = __uint_as_float((unsigned int)(u >> 32));
    return f;
}
__device__ __forceinline__ float grustep(float rv, float zv, float iv, float gv, float h) {
    float r = 1.f / (1.f + __expf(-rv));
    float z = 1.f / (1.f + __expf(-zv));
    float n = tanhf(iv + r * gv);
    return (1.f - z) * n + z * h;
}
#define BAR_H() asm volatile("bar.sync 1, 128;" ::: "memory")
#define BAR_F() asm volatile("bar.sync 2, 128;" ::: "memory")

// ================= init / CSR =================
__global__ void k_init() {
    int i = blockIdx.x * blockDim.x + threadIdx.x;
    if (i < NG) d_cnt[i] = 0.f;
    if (i < NG * D) d_pool[i] = 0.f;
}
__global__ void k_initCSR() {
    for (int i = blockIdx.x * blockDim.x + threadIdx.x; i < NROWS;
         i += gridDim.x * blockDim.x) {
        d_rcnt[i] = 0;
        d_rcur[i] = 0;
    }
}
__global__ void k_cnt2(const int* __restrict__ eidx, const int* __restrict__ eattr) {
    int e = blockIdx.x * blockDim.x + threadIdx.x;
    if (e >= N_EDGES) return;
    int key = eattr[e] * N_NODES + eidx[N_EDGES + e];
    atomicAdd(&d_rcnt[key], 1);
}
__global__ void k_scan1() {              // grid NBLK, block 1024
    __shared__ int ws[32];
    int i = blockIdx.x * 1024 + threadIdx.x;
    int lane = threadIdx.x & 31, w = threadIdx.x >> 5;
    int v = (i < NROWS) ? d_rcnt[i] : 0;
#pragma unroll
    for (int o = 16; o; o >>= 1) v += __shfl_down_sync(0xffffffffu, v, o);
    if (lane == 0) ws[w] = v;
    __syncthreads();
    if (w == 0) {
        int x = ws[lane];
#pragma unroll
        for (int o = 16; o; o >>= 1) x += __shfl_down_sync(0xffffffffu, x, o);
        if (lane == 0) d_bsum[blockIdx.x] = x;
    }
}
__global__ void k_scan2() {              // 1 block 1024: exclusive scan of bases
    __shared__ int ws[32];
    int i = threadIdx.x, lane = i & 31, w = i >> 5;
    int v = (i < NBLK) ? d_bsum[i] : 0;
    int inc = v;
#pragma unroll
    for (int o = 1; o < 32; o <<= 1) {
        int u = __shfl_up_sync(0xffffffffu, inc, o);
        if (lane >= o) inc += u;
    }
    if (lane == 31) ws[w] = inc;
    __syncthreads();
    if (w == 0) {
        int x = ws[lane];
#pragma unroll
        for (int o = 1; o < 32; o <<= 1) {
            int u = __shfl_up_sync(0xffffffffu, x, o);
            if (lane >= o) x += u;
        }
        ws[lane] = x;
    }
    __syncthreads();
    int excl = (w ? ws[w - 1] : 0) + inc - v;
    if (i < NBLK) d_bsum[i] = excl;
    if (i == 0) d_rowptr[NROWS] = N_EDGES;
}
__global__ void k_scan3() {              // grid NBLK, block 1024
    __shared__ int ws[32];
    int i = blockIdx.x * 1024 + threadIdx.x;
    int lane = threadIdx.x & 31, w = threadIdx.x >> 5;
    int v = (i < NROWS) ? d_rcnt[i] : 0;
    int inc = v;
#pragma unroll
    for (int o = 1; o < 32; o <<= 1) {
        int u = __shfl_up_sync(0xffffffffu, inc, o);
        if (lane >= o) inc += u;
    }
    if (lane == 31) ws[w] = inc;
    __syncthreads();
    if (w == 0) {
        int x = ws[lane];
#pragma unroll
        for (int o = 1; o < 32; o <<= 1) {
            int u = __shfl_up_sync(0xffffffffu, x, o);
            if (lane >= o) x += u;
        }
        ws[lane] = x;
    }
    __syncthreads();
    int excl = d_bsum[blockIdx.x] + (w ? ws[w - 1] : 0) + inc - v;
    if (i < NROWS) d_rowptr[i] = excl;
}
__global__ void k_fill2(const int* __restrict__ eidx, const int* __restrict__ eattr) {
    int e = blockIdx.x * blockDim.x + threadIdx.x;
    if (e >= N_EDGES) return;
    int t = eattr[e];
    int key = t * N_NODES + eidx[N_EDGES + e];
    int pos = d_rowptr[key] + atomicAdd(&d_rcur[key], 1);
    d_col[pos] = t * N_NODES + eidx[e];
}

// ================= h0 / Q / R / B prep (proven) =================
__global__ void k_h0(const float* __restrict__ x, const float* __restrict__ lw,
                     const float* __restrict__ lb) {
    __shared__ float Ash[64][17];
    __shared__ float Bsh[16][128];
    const int m0 = blockIdx.x * 64;
    const int tid = threadIdx.x;
    const int tj = tid & 31, tr = tid >> 5;
    float acc[8][4];
#pragma unroll
    for (int i = 0; i < 8; i++)
#pragma unroll
        for (int j = 0; j < 4; j++) acc[i][j] = 0.f;
    for (int c0 = 0; c0 < DIN; c0 += 16) {
#pragma unroll
        for (int i = 0; i < 4; i++) {
            int id = tid + i * 256, r = id >> 4, c = id & 15;
            int gm = m0 + r, gc = c0 + c;
            Ash[r][c] = (gm < N_NODES && gc < DIN) ? x[(size_t)gm * DIN + gc] : 0.f;
        }
#pragma unroll
        for (int i = 0; i < 8; i++) {
            int id = tid + i * 256, r = id >> 7, c = id & 127;
            int gc = c0 + r;
            Bsh[r][c] = (gc < DIN) ? lw[(size_t)gc * D + c] : 0.f;
        }
        __syncthreads();
#pragma unroll
        for (int k = 0; k < 16; k++) {
            float4 b = *(const float4*)&Bsh[k][tj * 4];
#pragma unroll
            for (int i = 0; i < 8; i++) {
                float a = Ash[tr * 8 + i][k];
                acc[i][0] += a * b.x; acc[i][1] += a * b.y;
                acc[i][2] += a * b.z; acc[i][3] += a * b.w;
            }
        }
        __syncthreads();
    }
    float4 lb4 = *(const float4*)&lb[tj * 4];
#pragma unroll
    for (int i = 0; i < 8; i++) {
        int gm = m0 + tr * 8 + i;
        if (gm >= N_NODES) continue;
        float4 v = make_float4(acc[i][0] + lb4.x, acc[i][1] + lb4.y,
                               acc[i][2] + lb4.z, acc[i][3] + lb4.w);
        size_t off = (size_t)gm * D + tj * 4;
        for (int t = 0; t < TT; t++)
            *(float4*)&d_H[(size_t)t * N_NODES * D + off] = v;
    }
}

__global__ void k_q(const float* __restrict__ W, const float* __restrict__ wih) {
    int ts = blockIdx.z, t = ts >> 3;
    int m0 = blockIdx.x * 64, n0 = blockIdx.y * 64;
    const float* A = W + (size_t)ts * D * D;
    const float* B = wih + (size_t)t * D3 * D;
    __shared__ float Ash[64][17];
    __shared__ float Bsh[16][65];
    const int tid = threadIdx.x, tj = tid & 15, tr = tid >> 4;
    float acc[4][4];
#pragma unroll
    for (int i = 0; i < 4; i++)
#pragma unroll
        for (int j = 0; j < 4; j++) acc[i][j] = 0.f;
    for (int c0 = 0; c0 < D; c0 += 16) {
#pragma unroll
        for (int i = 0; i < 4; i++) {
            int id = tid + i * 256, r = id >> 4, c = id & 15;
            Ash[r][c] = A[(size_t)(m0 + r) * D + c0 + c];
        }
#pragma unroll
        for (int i = 0; i < 4; i++) {
            int id = tid + i * 256, j = id >> 4, c = id & 15;
            Bsh[c][j] = B[(size_t)(n0 + j) * D + c0 + c];
        }
        __syncthreads();
#pragma unroll
        for (int k = 0; k < 16; k++) {
            float a[4], b[4];
#pragma unroll
            for (int i = 0; i < 4; i++) a[i] = Ash[tr * 4 + i][k];
#pragma unroll
            for (int j = 0; j < 4; j++) b[j] = Bsh[k][tj * 4 + j];
#pragma unroll
            for (int i = 0; i < 4; i++)
#pragma unroll
                for (int j = 0; j < 4; j++) acc[i][j] += a[i] * b[j];
        }
        __syncthreads();
    }
    float* Qo = d_Q + (size_t)ts * D * D3;
#pragma unroll
    for (int i = 0; i < 4; i++)
#pragma unroll
        for (int j = 0; j < 4; j++)
            Qo[(size_t)(m0 + tr * 4 + i) * D3 + n0 + tj * 4 + j] = acc[i][j];
}

__global__ void k_r(const float* __restrict__ whh) {
    int i = blockIdx.x * blockDim.x + threadIdx.x;
    if (i >= TT * D * D3) return;
    int t = i / (D * D3);
    int rem = i - t * (D * D3);
    int k = rem / D3, j = rem - k * D3;
    d_R[i] = whh[(size_t)t * D3 * D + (size_t)j * D + k];
}

__global__ void k_bsplit() {
    const size_t total = (size_t)TT * STEPS * 512 * 256;
    for (size_t idx = (size_t)blockIdx.x * blockDim.x + threadIdx.x; idx < total;
         idx += (size_t)gridDim.x * blockDim.x) {
        int k = (int)(idx & 255);
        int n = (int)((idx >> 8) & 511);
        int ts = (int)(idx >> 17);
        int t = ts >> 3;
        int gate = n >> 7, j = n & 127;
        float v;
        if (k < 128) {
            v = (gate < 3) ? d_Q[((size_t)ts * 128 + k) * 384 + gate * 128 + j] : 0.f;
        } else {
            int kh = k - 128;
            v = (gate < 2) ? d_R[((size_t)t * 128 + kh) * 384 + gate * 128 + j]
              : (gate == 2) ? 0.f
              : d_R[((size_t)t * 128 + kh) * 384 + 256 + j];
        }
        d_Bs[(size_t)ts * 512 * 256 + (size_t)n * 256 + k] = __float2bfloat16(v);
    }
}

// ================= CSR gather =================
__global__ void k_gather() {
    int r = (blockIdx.x * blockDim.x + threadIdx.x) >> 5;
    int lane = threadIdx.x & 31;
    if (r >= NROWS) return;
    int beg = d_rowptr[r], end = d_rowptr[r + 1];
    float4 acc = make_float4(0.f, 0.f, 0.f, 0.f);
    for (int e = beg; e < end; e++) {
        int g = d_col[e];
        float4 v = ((const float4*)(d_H + (size_t)g * D))[lane];
        acc.x += v.x; acc.y += v.y; acc.z += v.z; acc.w += v.w;
    }
    ((float4*)(d_S + (size_t)r * D))[lane] = acc;
}

// ================= dual-pipe gates kernel =================
// dyn smem (HMMA group): A [buf2][32][24] = 1536 elems ; B [buf2][512][24] @1536
#define SM_DYN  52224
#define GBK 8

__global__ void __launch_bounds__(256)
k_gates_mma(int s, const float* __restrict__ b_ih, const float* __restrict__ b_hh) {
    extern __shared__ __align__(16) char smem[];
    __shared__ float sbias[4][128];
    __shared__ unsigned long long Sd[GBK][36];
    __shared__ unsigned long long Hd[GBK][36];
    __shared__ float4 Qs[GBK * 96];
    __shared__ float4 Rs[GBK * 96];

    const int t = blockIdx.y;
    const int ts = t * STEPS + s;
    const int m0 = blockIdx.x * 64;
    const int tid = threadIdx.x;
    const uint32_t sb = smem_u32(smem);

    const float* __restrict__ Sp = d_S + (size_t)t * N_NODES * D;
    float* __restrict__ Hp = d_H + (size_t)t * N_NODES * D;

    if (tid < 128) {
        // ======== HMMA group: warps 0-3, nodes [m0, m0+32) ========
        const int lane = tid & 31, wn = tid >> 5;   // wn in [0,4)
        const __nv_bfloat16* __restrict__ Bg = d_Bs + (size_t)ts * 512 * 256;

        {
            const float* bi = b_ih + t * D3;
            const float* bh = b_hh + t * D3;
            sbias[0][tid] = bi[tid] + bh[tid];
            sbias[1][tid] = bi[128 + tid] + bh[128 + tid];
            sbias[2][tid] = bi[256 + tid];
            sbias[3][tid] = bh[256 + tid];
        }

        float acc[4][2][4][4];
#pragma unroll
        for (int a = 0; a < 4; a++)
#pragma unroll
            for (int b = 0; b < 2; b++)
#pragma unroll
                for (int c = 0; c < 4; c++)
#pragma unroll
                    for (int d = 0; d < 4; d++) acc[a][b][c][d] = 0.f;

        const int arow = tid >> 2, ag4 = tid & 3;   // 32 rows x 4 k-groups
        const int anode = m0 + arow;
        float4 av;
        uint4 bv[6];
        int bn[6];

        auto loadG = [&](int ks) {
            int kg = ks * 16 + ag4 * 4;
            if (anode < N_NODES) {
                const float* src = (kg < 128) ? (Sp + (size_t)anode * D + kg)
                                              : (Hp + (size_t)anode * D + (kg - 128));
                av = *(const float4*)src;
            } else {
                av = make_float4(0.f, 0.f, 0.f, 0.f);
            }
#pragma unroll
            for (int i = 0; i < 6; i++) {
                int id = tid + i * 128;              // 768 uint4
                int row = id >> 1, half = id & 1;
                int n = row + ((ks >= 8 && row >= 256) ? 128 : 0);
                bn[i] = n;
                bv[i] = *(const uint4*)(Bg + (size_t)n * 256 + ks * 16 + half * 8);
            }
        };
        auto storeS = [&](int buf) {
            unsigned hi0 = bf2pack(av.x, av.y);
            unsigned hi1 = bf2pack(av.z, av.w);
            *(uint2*)(smem + (uint32_t)(((buf * 32 + arow) * 24 + ag4 * 4) * 2)) =
                make_uint2(hi0, hi1);
#pragma unroll
            for (int i = 0; i < 6; i++) {
                int id = tid + i * 128;
                int half = id & 1;
                uint32_t off = (uint32_t)((1536 + (buf * 512 + bn[i]) * 24 + half * 8) * 2);
                *(uint4*)(smem + off) = bv[i];
            }
        };
        auto compute = [&](int cur, int ks) {
            uint32_t ah[2][4];
            const int arl = (lane & 7) + ((lane >> 3) & 1) * 8;
            const int ako = (lane >> 4) * 8;
#pragma unroll
            for (int mt = 0; mt < 2; mt++) {
                int rb = mt * 16;
                ldsm4(ah[mt], sb + (uint32_t)(((cur * 32 + rb + arl) * 24 + ako) * 2));
            }
            const int bnl = (lane & 7) + (lane >> 4) * 8;
            const int bko = ((lane >> 3) & 1) * 8;
#pragma unroll
            for (int gi = 0; gi < 4; gi++) {
                if (gi == 2 && ks >= 8) continue;
                if (gi == 3 && ks < 8) continue;
#pragma unroll
                for (int nt2 = 0; nt2 < 2; nt2++) {
                    int nb = gi * 128 + wn * 32 + nt2 * 16;
                    uint32_t bh[4];
                    ldsm4(bh, sb + (uint32_t)((1536 + (cur * 512 + nb + bnl) * 24 + bko) * 2));
#pragma unroll
                    for (int mt = 0; mt < 2; mt++)
#pragma unroll
                        for (int sub = 0; sub < 2; sub++)
                            mma16816(acc[gi][mt][nt2 * 2 + sub], ah[mt],
                                     bh[sub * 2], bh[sub * 2 + 1]);
                }
            }
        };

        loadG(0);
        storeS(0);
        BAR_H();
        for (int ks = 0; ks < 16; ks++) {
            int cur = ks & 1;
            if (ks < 15) loadG(ks + 1);
            compute(cur, ks);
            if (ks < 15) storeS(cur ^ 1);
            BAR_H();
        }

        // epilogue (proven mapping, wm removed)
        const int g = lane >> 2, tig = lane & 3;
#pragma unroll
        for (int mt = 0; mt < 2; mt++) {
            int rbase = m0 + mt * 16 + g;
#pragma unroll
            for (int half = 0; half < 2; half++) {
                int row = rbase + half * 8;
                if (row >= N_NODES) continue;
                float* hrow = Hp + (size_t)row * D;
#pragma unroll
                for (int nt = 0; nt < 4; nt++) {
                    int j0 = wn * 32 + nt * 8 + tig * 2;
                    int c0 = half * 2;
                    float h0 = hrow[j0], h1 = hrow[j0 + 1];
                    float o0 = grustep(acc[0][mt][nt][c0] + sbias[0][j0],
                                       acc[1][mt][nt][c0] + sbias[1][j0],
                                       acc[2][mt][nt][c0] + sbias[2][j0],
                                       acc[3][mt][nt][c0] + sbias[3][j0], h0);
                    float o1 = grustep(acc[0][mt][nt][c0 + 1] + sbias[0][j0 + 1],
                                       acc[1][mt][nt][c0 + 1] + sbias[1][j0 + 1],
                                       acc[2][mt][nt][c0 + 1] + sbias[2][j0 + 1],
                                       acc[3][mt][nt][c0 + 1] + sbias[3][j0 + 1], h1);
                    hrow[j0] = o0;
                    hrow[j0 + 1] = o1;
                }
            }
        }
    } else {
        // ======== FFMA2 group: warps 4-7, nodes [m0+32, m0+64) ========
        const int t2 = tid - 128;
        const int tj = t2 & 31, tr = t2 >> 5;        // 32 col-grps x 4 row-grps
        const int mf = m0 + 32;
        const float* __restrict__ Qp = d_Q + (size_t)ts * D * D3;
        const float* __restrict__ Rp = d_R + (size_t)t * D * D3;

        unsigned long long aR[8][2], aZ[8][2], aN[8][2], aH[8][2];
        {
            const float* bi = b_ih + t * D3;
            const float* bh = b_hh + t * D3;
            float vR[4], vZ[4], vN[4], vH[4];
#pragma unroll
            for (int j = 0; j < 4; j++) {
                int c = tj * 4 + j;
                vR[j] = bi[c] + bh[c];
                vZ[j] = bi[D + c] + bh[D + c];
                vN[j] = bi[2 * D + c];
                vH[j] = bh[2 * D + c];
            }
            unsigned long long pR0 = pack2(vR[0], vR[1]), pR1 = pack2(vR[2], vR[3]);
            unsigned long long pZ0 = pack2(vZ[0], vZ[1]), pZ1 = pack2(vZ[2], vZ[3]);
            unsigned long long pN0 = pack2(vN[0], vN[1]), pN1 = pack2(vN[2], vN[3]);
            unsigned long long pH0 = pack2(vH[0], vH[1]), pH1 = pack2(vH[2], vH[3]);
#pragma unroll
            for (int i = 0; i < 8; i++) {
                aR[i][0] = pR0; aR[i][1] = pR1;
                aZ[i][0] = pZ0; aZ[i][1] = pZ1;
                aN[i][0] = pN0; aN[i][1] = pN1;
                aH[i][0] = pH0; aH[i][1] = pH1;
            }
        }

        const int ldr = t2 >> 3, ldc = t2 & 7;       // 16 rows x 8 cols, x2 rows
        for (int c0 = 0; c0 < D; c0 += GBK) {
#pragma unroll
            for (int rr2 = 0; rr2 < 2; rr2++) {
                int row = ldr + rr2 * 16;
                int gm = mf + row;
                float sv = 0.f, hv = 0.f;
                if (gm < N_NODES) {
                    sv = Sp[(size_t)gm * D + c0 + ldc];
                    hv = Hp[(size_t)gm * D + c0 + ldc];
                }
                Sd[ldc][row] = dup2(sv);
                Hd[ldc][row] = dup2(hv);
            }
            {
                const float4* Qg = (const float4*)(Qp + (size_t)c0 * D3);
                const float4* Rg = (const float4*)(Rp + (size_t)c0 * D3);
#pragma unroll
                for (int i = 0; i < 6; i++) {
                    int id = t2 + i * 128;
                    Qs[id] = Qg[id];
                    Rs[id] = Rg[id];
                }
            }
            BAR_F();
#pragma unroll
            for (int k = 0; k < GBK; k++) {
                ulonglong2 qr = *(const ulonglong2*)&Qs[k * 96 + tj];
                ulonglong2 qz = *(const ulonglong2*)&Qs[k * 96 + 32 + tj];
                ulonglong2 qn = *(const ulonglong2*)&Qs[k * 96 + 64 + tj];
                ulonglong2 rr = *(const ulonglong2*)&Rs[k * 96 + tj];
                ulonglong2 rz = *(const ulonglong2*)&Rs[k * 96 + 32 + tj];
                ulonglong2 rn = *(const ulonglong2*)&Rs[k * 96 + 64 + tj];
#pragma unroll
                for (int i = 0; i < 8; i++) {
                    unsigned long long sp = Sd[k][tr * 8 + i];
                    unsigned long long hp = Hd[k][tr * 8 + i];
                    fma2(aR[i][0], sp, qr.x); fma2(aR[i][0], hp, rr.x);
                    fma2(aR[i][1], sp, qr.y); fma2(aR[i][1], hp, rr.y);
                    fma2(aZ[i][0], sp, qz.x); fma2(aZ[i][0], hp, rz.x);
                    fma2(aZ[i][1], sp, qz.y); fma2(aZ[i][1], hp, rz.y);
                    fma2(aN[i][0], sp, qn.x); fma2(aN[i][1], sp, qn.y);
                    fma2(aH[i][0], hp, rn.x); fma2(aH[i][1], hp, rn.y);
                }
            }
            BAR_F();
        }

#pragma unroll
        for (int i = 0; i < 8; i++) {
            int gm = mf + tr * 8 + i;
            if (gm >= N_NODES) continue;
            float* hp = Hp + (size_t)gm * D + tj * 4;
            float4 hold = *(const float4*)hp;
            float2 r0 = u2f2(aR[i][0]), r1 = u2f2(aR[i][1]);
            float2 z0 = u2f2(aZ[i][0]), z1 = u2f2(aZ[i][1]);
            float2 n0 = u2f2(aN[i][0]), n1 = u2f2(aN[i][1]);
            float2 g0 = u2f2(aH[i][0]), g1 = u2f2(aH[i][1]);
            float4 o;
            o.x = grustep(r0.x, z0.x, n0.x, g0.x, hold.x);
            o.y = grustep(r0.y, z0.y, n0.y, g0.y, hold.y);
            o.z = grustep(r1.x, z1.x, n1.x, g1.x, hold.z);
            o.w = grustep(r1.y, z1.y, n1.y, g1.y, hold.w);
            *(float4*)hp = o;
        }
    }
}

// ================= pooling / output =================
__global__ void k_pool(const int* __restrict__ batch) {
    int w = (blockIdx.x * blockDim.x + threadIdx.x) >> 5;
    int lane = threadIdx.x & 31;
    if (w >= N_NODES) return;
    int g = batch[w];
    float4 acc = make_float4(0.f, 0.f, 0.f, 0.f);
    for (int t = 0; t < TT; t++) {
        float4 v = ((const float4*)(d_H + ((size_t)t * N_NODES + w) * D))[lane];
        acc.x += v.x; acc.y += v.y; acc.z += v.z; acc.w += v.w;
    }
    float* p = d_pool + (size_t)g * D + lane * 4;
    atomicAdd(p + 0, acc.x); atomicAdd(p + 1, acc.y);
    atomicAdd(p + 2, acc.z); atomicAdd(p + 3, acc.w);
    if (lane == 0) atomicAdd(&d_cnt[g], 1.f);
}

__global__ void k_out(const float* __restrict__ cw, const float* __restrict__ cb,
                      float* __restrict__ out) {
    int g = blockIdx.x, c = threadIdx.y, lane = threadIdx.x;
    float inv = 1.f / fmaxf(d_cnt[g], 1.f);
    float acc = 0.f;
    for (int j = lane; j < D; j += 32)
        acc += d_pool[(size_t)g * D + j] * inv * cw[j * 2 + c];
#pragma unroll
    for (int o = 16; o; o >>= 1) acc += __shfl_down_sync(0xffffffffu, acc, o);
    if (lane == 0) out[g * 2 + c] = acc + cb[c];
}

// ================= launch =================
extern "C" void kernel_launch(void* const* d_in, const int* in_sizes, int n_in,
                              void* d_out, int out_size) {
    const float* x      = (const float*)d_in[0];
    const int*   eidx   = (const int*)d_in[1];
    const int*   eattr  = (const int*)d_in[2];
    const int*   batch  = (const int*)d_in[3];
    const float* lin_w  = (const float*)d_in[4];
    const float* lin_b  = (const float*)d_in[5];
    const float* ggnn_w = (const float*)d_in[6];
    const float* w_ih   = (const float*)d_in[7];
    const float* w_hh   = (const float*)d_in[8];
    const float* b_ih   = (const float*)d_in[9];
    const float* b_hh   = (const float*)d_in[10];
    const float* cls_w  = (const float*)d_in[11];
    const float* cls_b  = (const float*)d_in[12];
    float* out = (float*)d_out;
    (void)in_sizes; (void)n_in; (void)out_size;

    cudaFuncSetAttribute(k_gates_mma, cudaFuncAttributeMaxDynamicSharedMemorySize, SM_DYN);

    k_init<<<(NG * D + 255) / 256, 256>>>();
    k_initCSR<<<640, 256>>>();
    k_cnt2<<<(N_EDGES + 255) / 256, 256>>>(eidx, eattr);
    k_scan1<<<NBLK, 1024>>>();
    k_scan2<<<1, 1024>>>();
    k_scan3<<<NBLK, 1024>>>();
    k_fill2<<<(N_EDGES + 255) / 256, 256>>>(eidx, eattr);
    k_h0<<<(N_NODES + 63) / 64, 256>>>(x, lin_w, lin_b);
    {
        dim3 g(2, 6, TT * STEPS);
        k_q<<<g, 256>>>(ggnn_w, w_ih);
    }
    k_r<<<(TT * D * D3 + 255) / 256, 256>>>(w_hh);
    k_bsplit<<<2048, 256>>>();

    for (int s = 0; s < STEPS; s++) {
        k_gather<<<(NROWS * 32 + 255) / 256, 256>>>();
        dim3 gg(NTILE64, TT);
        k_gates_mma<<<gg, 256, SM_DYN>>>(s, b_ih, b_hh);
    }
    k_pool<<<(N_NODES * 32 + 255) / 256, 256>>>(batch);
    k_out<<<NG, dim3(32, 2)>>>(cls_w, cls_b, out);
}

// round 9
// speedup vs baseline: 1.8397x; 1.8397x over previous
#include <cuda_runtime.h>
#include <cuda_bf16.h>
#include <cstdint>

#define N_NODES 50000
#define N_EDGES 800000
#define DIN     369
#define D       128
#define D3      384
#define TT      13
#define STEPS   8
#define NG      256
#define NTILE64 782              // ceil(50000/64)
#define NROWS   (TT * N_NODES)   // 650000
#define NBLK    635              // ceil(NROWS/1024)
#define HSZ     ((size_t)TT * N_NODES * D)

// ================= static scratch =================
__device__ float d_H[2 * TT * N_NODES * D];             // ping-pong hidden (666 MB)
__device__ float d_Q[TT * STEPS * D * D3];              // [ts][k=128][n=384]
__device__ float d_R[TT * D * D3];                      // [t][k=128][j=384]
__device__ __align__(16) __nv_bfloat16 d_Bs[(size_t)TT * STEPS * 512 * 256]; // [ts][n][k]
__device__ int   d_rowptr[NROWS + 1];
__device__ int   d_rcnt[NROWS];
__device__ int   d_rcur[NROWS];
__device__ int   d_col[N_EDGES];
__device__ int   d_bsum[NBLK + 1];
__device__ float d_pool[NG * D];
__device__ float d_cnt[NG];

// ================= helpers =================
__device__ __forceinline__ uint32_t smem_u32(const void* p) {
    uint32_t a;
    asm("{ .reg .u64 t; cvta.to.shared.u64 t, %1; cvt.u32.u64 %0, t; }" : "=r"(a) : "l"(p));
    return a;
}
__device__ __forceinline__ void ldsm4(uint32_t a[4], uint32_t addr) {
    asm volatile("ldmatrix.sync.aligned.m8n8.x4.shared.b16 {%0,%1,%2,%3}, [%4];"
                 : "=r"(a[0]), "=r"(a[1]), "=r"(a[2]), "=r"(a[3]) : "r"(addr));
}
__device__ __forceinline__ void mma16816(float c[4], const uint32_t a[4],
                                         uint32_t b0, uint32_t b1) {
    asm volatile("mma.sync.aligned.m16n8k16.row.col.f32.bf16.bf16.f32 "
                 "{%0,%1,%2,%3}, {%4,%5,%6,%7}, {%8,%9}, {%0,%1,%2,%3};"
                 : "+f"(c[0]), "+f"(c[1]), "+f"(c[2]), "+f"(c[3])
                 : "r"(a[0]), "r"(a[1]), "r"(a[2]), "r"(a[3]), "r"(b0), "r"(b1));
}
__device__ __forceinline__ unsigned bf2pack(float a, float b) {
    __nv_bfloat16 x = __float2bfloat16(a), y = __float2bfloat16(b);
    return (unsigned)__bfloat16_as_ushort(x) | ((unsigned)__bfloat16_as_ushort(y) << 16);
}
__device__ __forceinline__ float grustep(float rv, float zv, float iv, float gv, float h) {
    float r = 1.f / (1.f + __expf(-rv));
    float z = 1.f / (1.f + __expf(-zv));
    float n = tanhf(iv + r * gv);
    return (1.f - z) * n + z * h;
}

// ================= init / CSR =================
__global__ void k_init() {
    int i = blockIdx.x * blockDim.x + threadIdx.x;
    if (i < NG) d_cnt[i] = 0.f;
    if (i < NG * D) d_pool[i] = 0.f;
}
__global__ void k_initCSR() {
    for (int i = blockIdx.x * blockDim.x + threadIdx.x; i < NROWS;
         i += gridDim.x * blockDim.x) {
        d_rcnt[i] = 0;
        d_rcur[i] = 0;
    }
}
__global__ void k_cnt2(const int* __restrict__ eidx, const int* __restrict__ eattr) {
    int e = blockIdx.x * blockDim.x + threadIdx.x;
    if (e >= N_EDGES) return;
    int key = eattr[e] * N_NODES + eidx[N_EDGES + e];
    atomicAdd(&d_rcnt[key], 1);
}
__global__ void k_scan1() {
    __shared__ int ws[32];
    int i = blockIdx.x * 1024 + threadIdx.x;
    int lane = threadIdx.x & 31, w = threadIdx.x >> 5;
    int v = (i < NROWS) ? d_rcnt[i] : 0;
#pragma unroll
    for (int o = 16; o; o >>= 1) v += __shfl_down_sync(0xffffffffu, v, o);
    if (lane == 0) ws[w] = v;
    __syncthreads();
    if (w == 0) {
        int x = ws[lane];
#pragma unroll
        for (int o = 16; o; o >>= 1) x += __shfl_down_sync(0xffffffffu, x, o);
        if (lane == 0) d_bsum[blockIdx.x] = x;
    }
}
__global__ void k_scan2() {
    __shared__ int ws[32];
    int i = threadIdx.x, lane = i & 31, w = i >> 5;
    int v = (i < NBLK) ? d_bsum[i] : 0;
    int inc = v;
#pragma unroll
    for (int o = 1; o < 32; o <<= 1) {
        int u = __shfl_up_sync(0xffffffffu, inc, o);
        if (lane >= o) inc += u;
    }
    if (lane == 31) ws[w] = inc;
    __syncthreads();
    if (w == 0) {
        int x = ws[lane];
#pragma unroll
        for (int o = 1; o < 32; o <<= 1) {
            int u = __shfl_up_sync(0xffffffffu, x, o);
            if (lane >= o) x += u;
        }
        ws[lane] = x;
    }
    __syncthreads();
    int excl = (w ? ws[w - 1] : 0) + inc - v;
    if (i < NBLK) d_bsum[i] = excl;
    if (i == 0) d_rowptr[NROWS] = N_EDGES;
}
__global__ void k_scan3() {
    __shared__ int ws[32];
    int i = blockIdx.x * 1024 + threadIdx.x;
    int lane = threadIdx.x & 31, w = threadIdx.x >> 5;
    int v = (i < NROWS) ? d_rcnt[i] : 0;
    int inc = v;
#pragma unroll
    for (int o = 1; o < 32; o <<= 1) {
        int u = __shfl_up_sync(0xffffffffu, inc, o);
        if (lane >= o) inc += u;
    }
    if (lane == 31) ws[w] = inc;
    __syncthreads();
    if (w == 0) {
        int x = ws[lane];
#pragma unroll
        for (int o = 1; o < 32; o <<= 1) {
            int u = __shfl_up_sync(0xffffffffu, x, o);
            if (lane >= o) x += u;
        }
        ws[lane] = x;
    }
    __syncthreads();
    int excl = d_bsum[blockIdx.x] + (w ? ws[w - 1] : 0) + inc - v;
    if (i < NROWS) d_rowptr[i] = excl;
}
__global__ void k_fill2(const int* __restrict__ eidx, const int* __restrict__ eattr) {
    int e = blockIdx.x * blockDim.x + threadIdx.x;
    if (e >= N_EDGES) return;
    int t = eattr[e];
    int key = t * N_NODES + eidx[N_EDGES + e];
    int pos = d_rowptr[key] + atomicAdd(&d_rcur[key], 1);
    d_col[pos] = t * N_NODES + eidx[e];
}

// ================= h0 / Q / R / B prep =================
__global__ void k_h0(const float* __restrict__ x, const float* __restrict__ lw,
                     const float* __restrict__ lb) {
    __shared__ float Ash[64][17];
    __shared__ float Bsh[16][128];
    const int m0 = blockIdx.x * 64;
    const int tid = threadIdx.x;
    const int tj = tid & 31, tr = tid >> 5;
    float acc[8][4];
#pragma unroll
    for (int i = 0; i < 8; i++)
#pragma unroll
        for (int j = 0; j < 4; j++) acc[i][j] = 0.f;
    for (int c0 = 0; c0 < DIN; c0 += 16) {
#pragma unroll
        for (int i = 0; i < 4; i++) {
            int id = tid + i * 256, r = id >> 4, c = id & 15;
            int gm = m0 + r, gc = c0 + c;
            Ash[r][c] = (gm < N_NODES && gc < DIN) ? x[(size_t)gm * DIN + gc] : 0.f;
        }
#pragma unroll
        for (int i = 0; i < 8; i++) {
            int id = tid + i * 256, r = id >> 7, c = id & 127;
            int gc = c0 + r;
            Bsh[r][c] = (gc < DIN) ? lw[(size_t)gc * D + c] : 0.f;
        }
        __syncthreads();
#pragma unroll
        for (int k = 0; k < 16; k++) {
            float4 b = *(const float4*)&Bsh[k][tj * 4];
#pragma unroll
            for (int i = 0; i < 8; i++) {
                float a = Ash[tr * 8 + i][k];
                acc[i][0] += a * b.x; acc[i][1] += a * b.y;
                acc[i][2] += a * b.z; acc[i][3] += a * b.w;
            }
        }
        __syncthreads();
    }
    float4 lb4 = *(const float4*)&lb[tj * 4];
#pragma unroll
    for (int i = 0; i < 8; i++) {
        int gm = m0 + tr * 8 + i;
        if (gm >= N_NODES) continue;
        float4 v = make_float4(acc[i][0] + lb4.x, acc[i][1] + lb4.y,
                               acc[i][2] + lb4.z, acc[i][3] + lb4.w);
        size_t off = (size_t)gm * D + tj * 4;
        for (int t = 0; t < TT; t++)
            *(float4*)&d_H[(size_t)t * N_NODES * D + off] = v;   // buf 0
    }
}

__global__ void k_q(const float* __restrict__ W, const float* __restrict__ wih) {
    int ts = blockIdx.z, t = ts >> 3;
    int m0 = blockIdx.x * 64, n0 = blockIdx.y * 64;
    const float* A = W + (size_t)ts * D * D;
    const float* B = wih + (size_t)t * D3 * D;
    __shared__ float Ash[64][17];
    __shared__ float Bsh[16][65];
    const int tid = threadIdx.x, tj = tid & 15, tr = tid >> 4;
    float acc[4][4];
#pragma unroll
    for (int i = 0; i < 4; i++)
#pragma unroll
        for (int j = 0; j < 4; j++) acc[i][j] = 0.f;
    for (int c0 = 0; c0 < D; c0 += 16) {
#pragma unroll
        for (int i = 0; i < 4; i++) {
            int id = tid + i * 256, r = id >> 4, c = id & 15;
            Ash[r][c] = A[(size_t)(m0 + r) * D + c0 + c];
        }
#pragma unroll
        for (int i = 0; i < 4; i++) {
            int id = tid + i * 256, j = id >> 4, c = id & 15;
            Bsh[c][j] = B[(size_t)(n0 + j) * D + c0 + c];
        }
        __syncthreads();
#pragma unroll
        for (int k = 0; k < 16; k++) {
            float a[4], b[4];
#pragma unroll
            for (int i = 0; i < 4; i++) a[i] = Ash[tr * 4 + i][k];
#pragma unroll
            for (int j = 0; j < 4; j++) b[j] = Bsh[k][tj * 4 + j];
#pragma unroll
            for (int i = 0; i < 4; i++)
#pragma unroll
                for (int j = 0; j < 4; j++) acc[i][j] += a[i] * b[j];
        }
        __syncthreads();
    }
    float* Qo = d_Q + (size_t)ts * D * D3;
#pragma unroll
    for (int i = 0; i < 4; i++)
#pragma unroll
        for (int j = 0; j < 4; j++)
            Qo[(size_t)(m0 + tr * 4 + i) * D3 + n0 + tj * 4 + j] = acc[i][j];
}

__global__ void k_r(const float* __restrict__ whh) {
    int i = blockIdx.x * blockDim.x + threadIdx.x;
    if (i >= TT * D * D3) return;
    int t = i / (D * D3);
    int rem = i - t * (D * D3);
    int k = rem / D3, j = rem - k * D3;
    d_R[i] = whh[(size_t)t * D3 * D + (size_t)j * D + k];
}

__global__ void k_bsplit() {
    const size_t total = (size_t)TT * STEPS * 512 * 256;
    for (size_t idx = (size_t)blockIdx.x * blockDim.x + threadIdx.x; idx < total;
         idx += (size_t)gridDim.x * blockDim.x) {
        int k = (int)(idx & 255);
        int n = (int)((idx >> 8) & 511);
        int ts = (int)(idx >> 17);
        int t = ts >> 3;
        int gate = n >> 7, j = n & 127;
        float v;
        if (k < 128) {
            v = (gate < 3) ? d_Q[((size_t)ts * 128 + k) * 384 + gate * 128 + j] : 0.f;
        } else {
            int kh = k - 128;
            v = (gate < 2) ? d_R[((size_t)t * 128 + kh) * 384 + gate * 128 + j]
              : (gate == 2) ? 0.f
              : d_R[((size_t)t * 128 + kh) * 384 + 256 + j];
        }
        d_Bs[(size_t)ts * 512 * 256 + (size_t)n * 256 + k] = __float2bfloat16(v);
    }
}

// ================= fused gather + HMMA gates kernel ===========
// dyn smem: A bf16 [buf2][64][24] = 3072 elems @0 ; B bf16 [buf2][512][24] @3072 elems
//           Sg fp32 [64][132] @ byte 55296  -> total 89088 bytes
#define SM_DYN  89088

__global__ void __launch_bounds__(256)
k_gates_mma(int s, const float* __restrict__ b_ih, const float* __restrict__ b_hh) {
    extern __shared__ __align__(16) char smem[];
    __shared__ float sbias[4][128];

    const int t = blockIdx.y;
    const int ts = t * STEPS + s;
    const int m0 = blockIdx.x * 64;
    const int tid = threadIdx.x;
    const int lane = tid & 31, wid = tid >> 5;
    const int wm = wid >> 2, wn = wid & 3;
    const uint32_t sb = smem_u32(smem);

    const float* __restrict__ Hr = d_H + (size_t)(s & 1) * HSZ + (size_t)t * N_NODES * D;
    float* __restrict__ Hw = d_H + (size_t)(1 - (s & 1)) * HSZ + (size_t)t * N_NODES * D;
    const float* __restrict__ HrAll = d_H + (size_t)(s & 1) * HSZ;
    const __nv_bfloat16* __restrict__ Bg = d_Bs + (size_t)ts * 512 * 256;
    float* Sg = (float*)(smem + 55296);

    if (tid < 128) {
        const float* bi = b_ih + t * D3;
        const float* bh = b_hh + t * D3;
        sbias[0][tid] = bi[tid] + bh[tid];
        sbias[1][tid] = bi[128 + tid] + bh[128 + tid];
        sbias[2][tid] = bi[256 + tid];
        sbias[3][tid] = bh[256 + tid];
    }

    // ---- gather: Sg[ln][0:128] = sum_{e in CSR row} Hr_all[col[e]] ----
#pragma unroll
    for (int rr = 0; rr < 8; rr++) {
        int ln = wid * 8 + rr;
        int node = m0 + ln;
        float4 acc4 = make_float4(0.f, 0.f, 0.f, 0.f);
        if (node < N_NODES) {
            int row = t * N_NODES + node;
            int beg = d_rowptr[row], end = d_rowptr[row + 1];
            for (int e = beg; e < end; e++) {
                int g = d_col[e];
                float4 v = ((const float4*)(HrAll + (size_t)g * D))[lane];
                acc4.x += v.x; acc4.y += v.y; acc4.z += v.z; acc4.w += v.w;
            }
        }
        *(float4*)(Sg + ln * 132 + lane * 4) = acc4;
    }
    __syncthreads();

    float acc[4][2][4][4];
#pragma unroll
    for (int a = 0; a < 4; a++)
#pragma unroll
        for (int b = 0; b < 2; b++)
#pragma unroll
            for (int c = 0; c < 4; c++)
#pragma unroll
                for (int d = 0; d < 4; d++) acc[a][b][c][d] = 0.f;

    const int arow = tid >> 2, ag4 = tid & 3;
    const int anode = m0 + arow;

    float4 av;
    uint4 bv[3];
    int bn[3];

    auto loadG = [&](int ks) {
        int kg = ks * 16 + ag4 * 4;
        if (kg < 128) {
            av = *(const float4*)(Sg + arow * 132 + kg);
        } else if (anode < N_NODES) {
            av = *(const float4*)(Hr + (size_t)anode * D + (kg - 128));
        } else {
            av = make_float4(0.f, 0.f, 0.f, 0.f);
        }
#pragma unroll
        for (int i = 0; i < 3; i++) {
            int id = tid + i * 256;
            int row = id >> 1, half = id & 1;
            int n = row + ((ks >= 8 && row >= 256) ? 128 : 0);
            bn[i] = n;
            bv[i] = *(const uint4*)(Bg + (size_t)n * 256 + ks * 16 + half * 8);
        }
    };
    auto storeS = [&](int buf) {
        unsigned hi0 = bf2pack(av.x, av.y);
        unsigned hi1 = bf2pack(av.z, av.w);
        *(uint2*)(smem + (uint32_t)(((buf * 64 + arow) * 24 + ag4 * 4) * 2)) =
            make_uint2(hi0, hi1);
#pragma unroll
        for (int i = 0; i < 3; i++) {
            int id = tid + i * 256;
            int half = id & 1;
            uint32_t off = (uint32_t)((3072 + (buf * 512 + bn[i]) * 24 + half * 8) * 2);
            *(uint4*)(smem + off) = bv[i];
        }
    };
    auto compute = [&](int cur, int ks) {
        uint32_t ah[2][4];
        const int arl = (lane & 7) + ((lane >> 3) & 1) * 8;
        const int ako = (lane >> 4) * 8;
#pragma unroll
        for (int mt = 0; mt < 2; mt++) {
            int rb = wm * 32 + mt * 16;
            ldsm4(ah[mt], sb + (uint32_t)(((cur * 64 + rb + arl) * 24 + ako) * 2));
        }
        const int bnl = (lane & 7) + (lane >> 4) * 8;
        const int bko = ((lane >> 3) & 1) * 8;
#pragma unroll
        for (int gi = 0; gi < 4; gi++) {
            if (gi == 2 && ks >= 8) continue;
            if (gi == 3 && ks < 8) continue;
#pragma unroll
            for (int nt2 = 0; nt2 < 2; nt2++) {
                int nb = gi * 128 + wn * 32 + nt2 * 16;
                uint32_t bh[4];
                ldsm4(bh, sb + (uint32_t)((3072 + (cur * 512 + nb + bnl) * 24 + bko) * 2));
#pragma unroll
                for (int mt = 0; mt < 2; mt++)
#pragma unroll
                    for (int sub = 0; sub < 2; sub++)
                        mma16816(acc[gi][mt][nt2 * 2 + sub], ah[mt],
                                 bh[sub * 2], bh[sub * 2 + 1]);
            }
        }
    };

    loadG(0);
    storeS(0);
    __syncthreads();
    for (int ks = 0; ks < 16; ks++) {
        int cur = ks & 1;
        if (ks < 15) loadG(ks + 1);
        compute(cur, ks);
        if (ks < 15) storeS(cur ^ 1);
        __syncthreads();
    }

    // ---- warp-local GRU epilogue: read Hr, write Hw ----
    const int g = lane >> 2, tig = lane & 3;
#pragma unroll
    for (int mt = 0; mt < 2; mt++) {
        int rbase = m0 + wm * 32 + mt * 16 + g;
#pragma unroll
        for (int half = 0; half < 2; half++) {
            int row = rbase + half * 8;
            if (row >= N_NODES) continue;
            const float* hrow = Hr + (size_t)row * D;
            float* wrow = Hw + (size_t)row * D;
#pragma unroll
            for (int nt = 0; nt < 4; nt++) {
                int j0 = wn * 32 + nt * 8 + tig * 2;
                int c0 = half * 2;
                float h0 = hrow[j0], h1 = hrow[j0 + 1];
                float o0 = grustep(acc[0][mt][nt][c0] + sbias[0][j0],
                                   acc[1][mt][nt][c0] + sbias[1][j0],
                                   acc[2][mt][nt][c0] + sbias[2][j0],
                                   acc[3][mt][nt][c0] + sbias[3][j0], h0);
                float o1 = grustep(acc[0][mt][nt][c0 + 1] + sbias[0][j0 + 1],
                                   acc[1][mt][nt][c0 + 1] + sbias[1][j0 + 1],
                                   acc[2][mt][nt][c0 + 1] + sbias[2][j0 + 1],
                                   acc[3][mt][nt][c0 + 1] + sbias[3][j0 + 1], h1);
                wrow[j0] = o0;
                wrow[j0 + 1] = o1;
            }
        }
    }
}

// ================= pooling / output (final H in buf 0) =================
__global__ void k_pool(const int* __restrict__ batch) {
    int w = (blockIdx.x * blockDim.x + threadIdx.x) >> 5;
    int lane = threadIdx.x & 31;
    if (w >= N_NODES) return;
    int g = batch[w];
    float4 acc = make_float4(0.f, 0.f, 0.f, 0.f);
    for (int t = 0; t < TT; t++) {
        float4 v = ((const float4*)(d_H + ((size_t)t * N_NODES + w) * D))[lane];
        acc.x += v.x; acc.y += v.y; acc.z += v.z; acc.w += v.w;
    }
    float* p = d_pool + (size_t)g * D + lane * 4;
    atomicAdd(p + 0, acc.x); atomicAdd(p + 1, acc.y);
    atomicAdd(p + 2, acc.z); atomicAdd(p + 3, acc.w);
    if (lane == 0) atomicAdd(&d_cnt[g], 1.f);
}

__global__ void k_out(const float* __restrict__ cw, const float* __restrict__ cb,
                      float* __restrict__ out) {
    int g = blockIdx.x, c = threadIdx.y, lane = threadIdx.x;
    float inv = 1.f / fmaxf(d_cnt[g], 1.f);
    float acc = 0.f;
    for (int j = lane; j < D; j += 32)
        acc += d_pool[(size_t)g * D + j] * inv * cw[j * 2 + c];
#pragma unroll
    for (int o = 16; o; o >>= 1) acc += __shfl_down_sync(0xffffffffu, acc, o);
    if (lane == 0) out[g * 2 + c] = acc + cb[c];
}

// ================= launch =================
extern "C" void kernel_launch(void* const* d_in, const int* in_sizes, int n_in,
                              void* d_out, int out_size) {
    const float* x      = (const float*)d_in[0];
    const int*   eidx   = (const int*)d_in[1];
    const int*   eattr  = (const int*)d_in[2];
    const int*   batch  = (const int*)d_in[3];
    const float* lin_w  = (const float*)d_in[4];
    const float* lin_b  = (const float*)d_in[5];
    const float* ggnn_w = (const float*)d_in[6];
    const float* w_ih   = (const float*)d_in[7];
    const float* w_hh   = (const float*)d_in[8];
    const float* b_ih   = (const float*)d_in[9];
    const float* b_hh   = (const float*)d_in[10];
    const float* cls_w  = (const float*)d_in[11];
    const float* cls_b  = (const float*)d_in[12];
    float* out = (float*)d_out;
    (void)in_sizes; (void)n_in; (void)out_size;

    cudaFuncSetAttribute(k_gates_mma, cudaFuncAttributeMaxDynamicSharedMemorySize, SM_DYN);

    k_init<<<(NG * D + 255) / 256, 256>>>();
    k_initCSR<<<640, 256>>>();
    k_cnt2<<<(N_EDGES + 255) / 256, 256>>>(eidx, eattr);
    k_scan1<<<NBLK, 1024>>>();
    k_scan2<<<1, 1024>>>();
    k_scan3<<<NBLK, 1024>>>();
    k_fill2<<<(N_EDGES + 255) / 256, 256>>>(eidx, eattr);
    k_h0<<<(N_NODES + 63) / 64, 256>>>(x, lin_w, lin_b);
    {
        dim3 g(2, 6, TT * STEPS);
        k_q<<<g, 256>>>(ggnn_w, w_ih);
    }
    k_r<<<(TT * D * D3 + 255) / 256, 256>>>(w_hh);
    k_bsplit<<<2048, 256>>>();

    for (int s = 0; s < STEPS; s++) {
        dim3 gg(NTILE64, TT);
        k_gates_mma<<<gg, 256, SM_DYN>>>(s, b_ih, b_hh);
    }
    k_pool<<<(N_NODES * 32 + 255) / 256, 256>>>(batch);
    k_out<<<NG, dim3(32, 2)>>>(cls_w, cls_b, out);
}